// round 2
// baseline (speedup 1.0000x reference)
#include <cuda_runtime.h>
#include <math.h>

#define Bsz 16
#define Ssz 512
#define Dsz 1024
#define Hh  16
#define Ff  4096
#define DH  64
#define MROWS (Bsz*Ssz)   // 8192

// ---------------- scratch (device-global; no allocation allowed) -------------
__device__ float g_X[MROWS*Dsz];   // current hidden
__device__ float g_Q[MROWS*Dsz];
__device__ float g_K[MROWS*Dsz];
__device__ float g_V[MROWS*Dsz];
__device__ float g_C[MROWS*Dsz];   // attention ctx
__device__ float g_T[MROWS*Dsz];   // pre-LN temp
__device__ float g_Hb[MROWS*Ff];   // FFN hidden

// ---------------- SGEMM: C = A[M,K] @ B[K,N] + bias (+Res) (+ReLU) ----------
// BM=BN=128, BK=8, 256 threads, 8x8 per thread, double-buffered smem.
template<bool RELU, bool RES>
__global__ void __launch_bounds__(256)
sgemm(const float* __restrict__ A, const float* __restrict__ Bm,
      const float* __restrict__ bias, const float* __restrict__ Res,
      float* __restrict__ C, int M, int N, int K)
{
    __shared__ float As[2][8][132];   // stored transposed: As[k][m]
    __shared__ float Bs[2][8][132];

    const int tid = threadIdx.x;
    const int bm  = blockIdx.y * 128;
    const int bn  = blockIdx.x * 128;
    const int tx  = tid & 15;
    const int ty  = tid >> 4;

    const int a_r = tid >> 1;          // 0..127
    const int a_c = (tid & 1) * 4;     // 0 or 4
    const int b_r = tid >> 5;          // 0..7
    const int b_c = (tid & 31) * 4;    // 0..124

    const float* Ap = A  + (size_t)(bm + a_r) * K + a_c;
    const float* Bp = Bm + (size_t)b_r * N + bn + b_c;

    float4 av = *(const float4*)Ap;
    float4 bv = *(const float4*)Bp;
    As[0][a_c+0][a_r] = av.x; As[0][a_c+1][a_r] = av.y;
    As[0][a_c+2][a_r] = av.z; As[0][a_c+3][a_r] = av.w;
    *(float4*)&Bs[0][b_r][b_c] = bv;
    __syncthreads();

    float acc[8][8];
    #pragma unroll
    for (int i = 0; i < 8; ++i)
        #pragma unroll
        for (int j = 0; j < 8; ++j) acc[i][j] = 0.f;

    const int nt = K >> 3;
    int stage = 0;
    for (int t = 0; t < nt; ++t) {
        if (t + 1 < nt) {
            av = *(const float4*)(Ap + (t + 1) * 8);
            bv = *(const float4*)(Bp + (size_t)(t + 1) * 8 * N);
        }
        #pragma unroll
        for (int k = 0; k < 8; ++k) {
            float4 a0 = *(const float4*)&As[stage][k][ty * 4];
            float4 a1 = *(const float4*)&As[stage][k][64 + ty * 4];
            float4 b0 = *(const float4*)&Bs[stage][k][tx * 4];
            float4 b1 = *(const float4*)&Bs[stage][k][64 + tx * 4];
            float ar[8] = {a0.x,a0.y,a0.z,a0.w,a1.x,a1.y,a1.z,a1.w};
            float br[8] = {b0.x,b0.y,b0.z,b0.w,b1.x,b1.y,b1.z,b1.w};
            #pragma unroll
            for (int i = 0; i < 8; ++i)
                #pragma unroll
                for (int j = 0; j < 8; ++j)
                    acc[i][j] += ar[i] * br[j];
        }
        if (t + 1 < nt) {
            stage ^= 1;
            As[stage][a_c+0][a_r] = av.x; As[stage][a_c+1][a_r] = av.y;
            As[stage][a_c+2][a_r] = av.z; As[stage][a_c+3][a_r] = av.w;
            *(float4*)&Bs[stage][b_r][b_c] = bv;
            __syncthreads();
        }
    }

    // epilogue
    const int c0 = bn + tx * 4;
    const int c1 = bn + 64 + tx * 4;
    float4 bi0 = *(const float4*)&bias[c0];
    float4 bi1 = *(const float4*)&bias[c1];
    #pragma unroll
    for (int i = 0; i < 8; ++i) {
        int row_in = (i < 4) ? (ty * 4 + i) : (64 + ty * 4 + (i - 4));
        size_t gr = (size_t)(bm + row_in) * N;
        float4 o0, o1;
        o0.x = acc[i][0] + bi0.x; o0.y = acc[i][1] + bi0.y;
        o0.z = acc[i][2] + bi0.z; o0.w = acc[i][3] + bi0.w;
        o1.x = acc[i][4] + bi1.x; o1.y = acc[i][5] + bi1.y;
        o1.z = acc[i][6] + bi1.z; o1.w = acc[i][7] + bi1.w;
        if (RES) {
            float4 r0 = *(const float4*)&Res[gr + c0];
            float4 r1 = *(const float4*)&Res[gr + c1];
            o0.x += r0.x; o0.y += r0.y; o0.z += r0.z; o0.w += r0.w;
            o1.x += r1.x; o1.y += r1.y; o1.z += r1.z; o1.w += r1.w;
        }
        if (RELU) {
            o0.x = fmaxf(o0.x, 0.f); o0.y = fmaxf(o0.y, 0.f);
            o0.z = fmaxf(o0.z, 0.f); o0.w = fmaxf(o0.w, 0.f);
            o1.x = fmaxf(o1.x, 0.f); o1.y = fmaxf(o1.y, 0.f);
            o1.z = fmaxf(o1.z, 0.f); o1.w = fmaxf(o1.w, 0.f);
        }
        *(float4*)&C[gr + c0] = o0;
        *(float4*)&C[gr + c1] = o1;
    }
}

// ---------------- flash attention ------------------------------------------
// grid: (S/64, B*H), 256 threads. Q/K/V/ctx layout: [b, s, h, d] (d=64 contig).
// Warp w owns q-rows w*8..w*8+7; lane owns keys {lane, lane+32}; P staging is
// warp-private in smem so only K/V loads need block syncs.
#define ATT_ROWSTRIDE 68
#define ATT_SMEM ((4*64*ATT_ROWSTRIDE + 64) * 4)

__global__ void __launch_bounds__(256)
attn_kernel(const float* __restrict__ Qg, const float* __restrict__ Kg,
            const float* __restrict__ Vg, float* __restrict__ Cg)
{
    extern __shared__ float sm[];
    float* Qs = sm;
    float* Ks = sm + 64 * ATT_ROWSTRIDE;
    float* Vs = sm + 2 * 64 * ATT_ROWSTRIDE;
    float* Ps = sm + 3 * 64 * ATT_ROWSTRIDE;
    float* Cs = sm + 4 * 64 * ATT_ROWSTRIDE;   // per-row scalar (corr / lsum)

    const int tid  = threadIdx.x;
    const int w    = tid >> 5;
    const int lane = tid & 31;
    const int qt   = blockIdx.x;         // 0..7
    const int bh   = blockIdx.y;         // 0..255
    const int b    = bh >> 4;
    const int h    = bh & 15;

    const size_t headoff = ((size_t)b * Ssz * Hh + h) * DH;
    const int sstride = Hh * DH;         // 1024 floats per sequence step

    // load Q tile [64 x 64]
    #pragma unroll
    for (int i = 0; i < 4; ++i) {
        int idx = tid + i * 256;
        int r = idx >> 4, c4 = (idx & 15) * 4;
        *(float4*)&Qs[r * ATT_ROWSTRIDE + c4] =
            *(const float4*)&Qg[headoff + (size_t)(qt * 64 + r) * sstride + c4];
    }

    float m[8], lden[8];
    #pragma unroll
    for (int r = 0; r < 8; ++r) { m[r] = -1e30f; lden[r] = 0.f; }
    float o0[8], o1[8];
    #pragma unroll
    for (int c = 0; c < 8; ++c) { o0[c] = 0.f; o1[c] = 0.f; }

    const int row0 = w * 8 + ((lane >> 3) << 1);  // this lane's O rows
    const int colA = (lane & 7) * 4;              // O cols colA..+3, colA+32..+35

    for (int kb = 0; kb < 8; ++kb) {
        __syncthreads();     // prior-iter smem reads done (covers Q load at kb=0)
        #pragma unroll
        for (int i = 0; i < 4; ++i) {
            int idx = tid + i * 256;
            int r = idx >> 4, c4 = (idx & 15) * 4;
            size_t g = headoff + (size_t)(kb * 64 + r) * sstride + c4;
            *(float4*)&Ks[r * ATT_ROWSTRIDE + c4] = *(const float4*)&Kg[g];
            *(float4*)&Vs[r * ATT_ROWSTRIDE + c4] = *(const float4*)&Vg[g];
        }
        __syncthreads();

        // scores: rows w*8..+7 vs keys lane, lane+32
        float s0[8], s1[8];
        #pragma unroll
        for (int r = 0; r < 8; ++r) { s0[r] = 0.f; s1[r] = 0.f; }
        #pragma unroll
        for (int d4 = 0; d4 < 64; d4 += 4) {
            float4 k0 = *(const float4*)&Ks[lane * ATT_ROWSTRIDE + d4];
            float4 k1 = *(const float4*)&Ks[(lane + 32) * ATT_ROWSTRIDE + d4];
            #pragma unroll
            for (int r = 0; r < 8; ++r) {
                float4 q = *(const float4*)&Qs[(w * 8 + r) * ATT_ROWSTRIDE + d4];
                s0[r] += q.x * k0.x + q.y * k0.y + q.z * k0.z + q.w * k0.w;
                s1[r] += q.x * k1.x + q.y * k1.y + q.z * k1.z + q.w * k1.w;
            }
        }

        // online softmax per row (all lanes hold uniform m/l copies)
        #pragma unroll
        for (int r = 0; r < 8; ++r) {
            float sa = s0[r] * 0.125f;
            float sb = s1[r] * 0.125f;
            float mx = fmaxf(sa, sb);
            #pragma unroll
            for (int off = 16; off; off >>= 1)
                mx = fmaxf(mx, __shfl_xor_sync(0xffffffffu, mx, off));
            float mnew = fmaxf(m[r], mx);
            float p0 = __expf(sa - mnew);
            float p1 = __expf(sb - mnew);
            float ps = p0 + p1;
            #pragma unroll
            for (int off = 16; off; off >>= 1)
                ps += __shfl_xor_sync(0xffffffffu, ps, off);
            float corr = __expf(m[r] - mnew);
            lden[r] = lden[r] * corr + ps;
            m[r] = mnew;
            Ps[(w * 8 + r) * ATT_ROWSTRIDE + lane]      = p0;
            Ps[(w * 8 + r) * ATT_ROWSTRIDE + lane + 32] = p1;
            if (lane == 0) Cs[w * 8 + r] = corr;
        }
        __syncwarp();

        float cr0 = Cs[row0];
        float cr1 = Cs[row0 + 1];
        #pragma unroll
        for (int c = 0; c < 8; ++c) { o0[c] *= cr0; o1[c] *= cr1; }

        // O += P @ V  (warp-private Ps rows, shared Vs)
        #pragma unroll
        for (int kk4 = 0; kk4 < 64; kk4 += 4) {
            float4 pv0 = *(const float4*)&Ps[row0 * ATT_ROWSTRIDE + kk4];
            float4 pv1 = *(const float4*)&Ps[(row0 + 1) * ATT_ROWSTRIDE + kk4];
            float pa[4] = {pv0.x, pv0.y, pv0.z, pv0.w};
            float pb[4] = {pv1.x, pv1.y, pv1.z, pv1.w};
            #pragma unroll
            for (int j = 0; j < 4; ++j) {
                float4 va = *(const float4*)&Vs[(kk4 + j) * ATT_ROWSTRIDE + colA];
                float4 vb = *(const float4*)&Vs[(kk4 + j) * ATT_ROWSTRIDE + colA + 32];
                o0[0] += pa[j] * va.x; o0[1] += pa[j] * va.y;
                o0[2] += pa[j] * va.z; o0[3] += pa[j] * va.w;
                o0[4] += pa[j] * vb.x; o0[5] += pa[j] * vb.y;
                o0[6] += pa[j] * vb.z; o0[7] += pa[j] * vb.w;
                o1[0] += pb[j] * va.x; o1[1] += pb[j] * va.y;
                o1[2] += pb[j] * va.z; o1[3] += pb[j] * va.w;
                o1[4] += pb[j] * vb.x; o1[5] += pb[j] * vb.y;
                o1[6] += pb[j] * vb.z; o1[7] += pb[j] * vb.w;
            }
        }
        __syncwarp();   // Ps/Cs reads done before next-iter rewrite by this warp
    }

    // finalize: divide by l, write ctx
    if (lane == 0) {
        #pragma unroll
        for (int r = 0; r < 8; ++r) Cs[w * 8 + r] = lden[r];
    }
    __syncwarp();
    float inv0 = 1.f / Cs[row0];
    float inv1 = 1.f / Cs[row0 + 1];

    size_t base0 = headoff + (size_t)(qt * 64 + row0) * sstride;
    size_t base1 = base0 + sstride;
    float4 out;
    out.x = o0[0]*inv0; out.y = o0[1]*inv0; out.z = o0[2]*inv0; out.w = o0[3]*inv0;
    *(float4*)&Cg[base0 + colA] = out;
    out.x = o0[4]*inv0; out.y = o0[5]*inv0; out.z = o0[6]*inv0; out.w = o0[7]*inv0;
    *(float4*)&Cg[base0 + colA + 32] = out;
    out.x = o1[0]*inv1; out.y = o1[1]*inv1; out.z = o1[2]*inv1; out.w = o1[3]*inv1;
    *(float4*)&Cg[base1 + colA] = out;
    out.x = o1[4]*inv1; out.y = o1[5]*inv1; out.z = o1[6]*inv1; out.w = o1[7]*inv1;
    *(float4*)&Cg[base1 + colA + 32] = out;
}

// ---------------- LayerNorm (one block per row of 1024) ---------------------
__device__ __forceinline__ float block_sum(float v, float* red)
{
    #pragma unroll
    for (int off = 16; off; off >>= 1)
        v += __shfl_xor_sync(0xffffffffu, v, off);
    __syncthreads();                 // guard previous red use
    if ((threadIdx.x & 31) == 0) red[threadIdx.x >> 5] = v;
    __syncthreads();
    return red[0]+red[1]+red[2]+red[3]+red[4]+red[5]+red[6]+red[7];
}

__global__ void __launch_bounds__(256)
ln_kernel(const float* __restrict__ X, const float* __restrict__ gw,
          const float* __restrict__ bw, float* __restrict__ Y)
{
    __shared__ float red[8];
    const int row = blockIdx.x;
    const int tid = threadIdx.x;
    const size_t base = (size_t)row * Dsz + tid * 4;

    float4 v = *(const float4*)&X[base];
    float mean = block_sum(v.x + v.y + v.z + v.w, red) * (1.f / Dsz);
    float dx = v.x - mean, dy = v.y - mean, dz = v.z - mean, dw = v.w - mean;
    float var = block_sum(dx*dx + dy*dy + dz*dz + dw*dw, red) * (1.f / Dsz);
    float inv = rsqrtf(var + 1e-6f);

    float4 g4 = *(const float4*)&gw[tid * 4];
    float4 b4 = *(const float4*)&bw[tid * 4];
    float4 o;
    o.x = dx * inv * g4.x + b4.x;
    o.y = dy * inv * g4.y + b4.y;
    o.z = dz * inv * g4.z + b4.z;
    o.w = dw * inv * g4.w + b4.w;
    *(float4*)&Y[base] = o;
}

// ---------------- driver -----------------------------------------------------
extern "C" void kernel_launch(void* const* d_in, const int* in_sizes, int n_in,
                              void* d_out, int out_size)
{
    const float* hid  = (const float*)d_in[0];
    const float* Wq   = (const float*)d_in[1];
    const float* bq   = (const float*)d_in[2];
    const float* Wk   = (const float*)d_in[3];
    const float* bk   = (const float*)d_in[4];
    const float* Wv   = (const float*)d_in[5];
    const float* bv   = (const float*)d_in[6];
    const float* Wp   = (const float*)d_in[7];
    const float* bp   = (const float*)d_in[8];
    const float* g1   = (const float*)d_in[9];
    const float* be1  = (const float*)d_in[10];
    const float* W1   = (const float*)d_in[11];
    const float* b1   = (const float*)d_in[12];
    const float* W2   = (const float*)d_in[13];
    const float* b2   = (const float*)d_in[14];
    const float* g2   = (const float*)d_in[15];
    const float* be2  = (const float*)d_in[16];

    float *pX, *pQ, *pK, *pV, *pC, *pT, *pH;
    cudaGetSymbolAddress((void**)&pX, g_X);
    cudaGetSymbolAddress((void**)&pQ, g_Q);
    cudaGetSymbolAddress((void**)&pK, g_K);
    cudaGetSymbolAddress((void**)&pV, g_V);
    cudaGetSymbolAddress((void**)&pC, g_C);
    cudaGetSymbolAddress((void**)&pT, g_T);
    cudaGetSymbolAddress((void**)&pH, g_Hb);

    cudaFuncSetAttribute(attn_kernel,
                         cudaFuncAttributeMaxDynamicSharedMemorySize, ATT_SMEM);

    const size_t hbytes = sizeof(float) * (size_t)MROWS * Dsz;
    cudaMemcpyAsync(pX, hid, hbytes, cudaMemcpyDeviceToDevice);

    dim3 gD(Dsz / 128, MROWS / 128);   // (8, 64)
    dim3 gF(Ff  / 128, MROWS / 128);   // (32, 64)
    dim3 gA(Ssz / 64, Bsz * Hh);       // (8, 256)

    for (int l = 0; l < 4; ++l) {
        const float* wq = Wq + (size_t)l * Dsz * Dsz;
        const float* wk = Wk + (size_t)l * Dsz * Dsz;
        const float* wv = Wv + (size_t)l * Dsz * Dsz;
        const float* wp = Wp + (size_t)l * Dsz * Dsz;
        const float* w1 = W1 + (size_t)l * Dsz * Ff;
        const float* w2 = W2 + (size_t)l * Ff * Dsz;

        sgemm<false,false><<<gD, 256>>>(pX, wq, bq + l*Dsz, nullptr, pQ, MROWS, Dsz, Dsz);
        sgemm<false,false><<<gD, 256>>>(pX, wk, bk + l*Dsz, nullptr, pK, MROWS, Dsz, Dsz);
        sgemm<false,false><<<gD, 256>>>(pX, wv, bv + l*Dsz, nullptr, pV, MROWS, Dsz, Dsz);

        attn_kernel<<<gA, 256, ATT_SMEM>>>(pQ, pK, pV, pC);

        sgemm<false,true ><<<gD, 256>>>(pC, wp, bp + l*Dsz, pX, pT, MROWS, Dsz, Dsz);
        ln_kernel<<<MROWS, 256>>>(pT, g1 + l*Dsz, be1 + l*Dsz, pX);

        sgemm<true ,false><<<gF, 256>>>(pX, w1, b1 + l*Ff, nullptr, pH, MROWS, Ff, Dsz);
        sgemm<false,true ><<<gD, 256>>>(pH, w2, b2 + l*Dsz, pX, pT, MROWS, Dsz, Ff);
        ln_kernel<<<MROWS, 256>>>(pT, g2 + l*Dsz, be2 + l*Dsz, pX);
    }

    cudaMemcpyAsync((float*)d_out, pX, hbytes, cudaMemcpyDeviceToDevice);
}

// round 3
// speedup vs baseline: 1.6556x; 1.6556x over previous
#include <cuda_runtime.h>
#include <math.h>
#include <stdint.h>

#define Bsz 16
#define Ssz 512
#define Dsz 1024
#define Hh  16
#define Ff  4096
#define DH  64
#define MROWS (Bsz*Ssz)   // 8192

// ---------------- scratch (device-global; no allocation allowed) -------------
__device__ float g_X[MROWS*Dsz];   // current hidden
__device__ float g_Q[MROWS*Dsz];
__device__ float g_K[MROWS*Dsz];
__device__ float g_V[MROWS*Dsz];
__device__ float g_C[MROWS*Dsz];   // attention ctx
__device__ float g_T[MROWS*Dsz];   // pre-LN temp
__device__ float g_Hb[MROWS*Ff];   // FFN hidden

// ---------------- tf32 helpers ----------------------------------------------
__device__ __forceinline__ uint32_t f2tf32(float x) {
    uint32_t u;
    asm("cvt.rna.tf32.f32 %0, %1;" : "=r"(u) : "f"(x));
    return u;
}

__device__ __forceinline__ void mma_tf32(float& c0, float& c1, float& c2, float& c3,
                                         uint32_t a0, uint32_t a1, uint32_t a2, uint32_t a3,
                                         uint32_t b0, uint32_t b1) {
    asm volatile(
        "mma.sync.aligned.m16n8k8.row.col.f32.tf32.tf32.f32 "
        "{%0,%1,%2,%3}, {%4,%5,%6,%7}, {%8,%9}, {%0,%1,%2,%3};"
        : "+f"(c0), "+f"(c1), "+f"(c2), "+f"(c3)
        : "r"(a0), "r"(a1), "r"(a2), "r"(a3), "r"(b0), "r"(b1));
}

// ---------------- TF32 tensor-core GEMM -------------------------------------
// C[M,N] = A[M,K] @ B[K,N] + bias (+Res) (+ReLU). fp32 in/out, tf32 mma.
// BM=BN=128, BK=16, 256 thr = 8 warps (2 m x 4 n), warp tile 64x32.
#define GPAD 132   // smem row stride (words)

template<bool RELU, bool RES>
__global__ void __launch_bounds__(256)
gemm_tf32(const float* __restrict__ A, const float* __restrict__ Bm,
          const float* __restrict__ bias, const float* __restrict__ Res,
          float* __restrict__ C, int M, int N, int K)
{
    __shared__ __align__(16) uint32_t As[2][16][GPAD];  // k-major: As[k][m]
    __shared__ __align__(16) uint32_t Bs[2][16][GPAD];  // natural: Bs[k][n]

    const int tid  = threadIdx.x;
    const int warp = tid >> 5;
    const int lane = tid & 31;
    const int wm   = warp >> 2;        // 0..1
    const int wn   = warp & 3;         // 0..3
    const int g    = lane >> 2;        // 0..7 (fragment group)
    const int tg   = lane & 3;         // 0..3 (fragment thread-in-group)

    const int bm = blockIdx.y * 128;
    const int bn = blockIdx.x * 128;

    // staging indices
    const int a_r = tid >> 1;          // 0..127
    const int a_c = (tid & 1) * 8;     // 0 or 8
    const int b_r = tid >> 4;          // 0..15
    const int b_c = (tid & 15) * 8;    // 0..120

    const float* Ap = A  + (size_t)(bm + a_r) * K + a_c;
    const float* Bp = Bm + (size_t)b_r * N + bn + b_c;

    // stage 0
    {
        float4 av0 = *(const float4*)Ap;
        float4 av1 = *(const float4*)(Ap + 4);
        float4 bv0 = *(const float4*)Bp;
        float4 bv1 = *(const float4*)(Bp + 4);
        As[0][a_c+0][a_r] = f2tf32(av0.x); As[0][a_c+1][a_r] = f2tf32(av0.y);
        As[0][a_c+2][a_r] = f2tf32(av0.z); As[0][a_c+3][a_r] = f2tf32(av0.w);
        As[0][a_c+4][a_r] = f2tf32(av1.x); As[0][a_c+5][a_r] = f2tf32(av1.y);
        As[0][a_c+6][a_r] = f2tf32(av1.z); As[0][a_c+7][a_r] = f2tf32(av1.w);
        uint4 bu0 = make_uint4(f2tf32(bv0.x), f2tf32(bv0.y), f2tf32(bv0.z), f2tf32(bv0.w));
        uint4 bu1 = make_uint4(f2tf32(bv1.x), f2tf32(bv1.y), f2tf32(bv1.z), f2tf32(bv1.w));
        *(uint4*)&Bs[0][b_r][b_c]     = bu0;
        *(uint4*)&Bs[0][b_r][b_c + 4] = bu1;
    }
    __syncthreads();

    float acc[4][4][4];
    #pragma unroll
    for (int i = 0; i < 4; ++i)
        #pragma unroll
        for (int j = 0; j < 4; ++j)
            #pragma unroll
            for (int e = 0; e < 4; ++e) acc[i][j][e] = 0.f;

    const int nt = K >> 4;
    int stage = 0;
    for (int t = 0; t < nt; ++t) {
        float4 av0, av1, bv0, bv1;
        if (t + 1 < nt) {
            av0 = *(const float4*)(Ap + (t + 1) * 16);
            av1 = *(const float4*)(Ap + (t + 1) * 16 + 4);
            bv0 = *(const float4*)(Bp + (size_t)(t + 1) * 16 * N);
            bv1 = *(const float4*)(Bp + (size_t)(t + 1) * 16 * N + 4);
        }

        #pragma unroll
        for (int ks = 0; ks < 16; ks += 8) {
            uint32_t af[4][4];
            uint32_t bf[4][2];
            #pragma unroll
            for (int mi = 0; mi < 4; ++mi) {
                int rm = wm * 64 + mi * 16 + g;
                af[mi][0] = As[stage][ks + tg    ][rm];
                af[mi][1] = As[stage][ks + tg    ][rm + 8];
                af[mi][2] = As[stage][ks + tg + 4][rm];
                af[mi][3] = As[stage][ks + tg + 4][rm + 8];
            }
            #pragma unroll
            for (int nj = 0; nj < 4; ++nj) {
                int cn = wn * 32 + nj * 8 + g;
                bf[nj][0] = Bs[stage][ks + tg    ][cn];
                bf[nj][1] = Bs[stage][ks + tg + 4][cn];
            }
            #pragma unroll
            for (int mi = 0; mi < 4; ++mi)
                #pragma unroll
                for (int nj = 0; nj < 4; ++nj)
                    mma_tf32(acc[mi][nj][0], acc[mi][nj][1], acc[mi][nj][2], acc[mi][nj][3],
                             af[mi][0], af[mi][1], af[mi][2], af[mi][3],
                             bf[nj][0], bf[nj][1]);
        }

        if (t + 1 < nt) {
            stage ^= 1;
            As[stage][a_c+0][a_r] = f2tf32(av0.x); As[stage][a_c+1][a_r] = f2tf32(av0.y);
            As[stage][a_c+2][a_r] = f2tf32(av0.z); As[stage][a_c+3][a_r] = f2tf32(av0.w);
            As[stage][a_c+4][a_r] = f2tf32(av1.x); As[stage][a_c+5][a_r] = f2tf32(av1.y);
            As[stage][a_c+6][a_r] = f2tf32(av1.z); As[stage][a_c+7][a_r] = f2tf32(av1.w);
            uint4 bu0 = make_uint4(f2tf32(bv0.x), f2tf32(bv0.y), f2tf32(bv0.z), f2tf32(bv0.w));
            uint4 bu1 = make_uint4(f2tf32(bv1.x), f2tf32(bv1.y), f2tf32(bv1.z), f2tf32(bv1.w));
            *(uint4*)&Bs[stage][b_r][b_c]     = bu0;
            *(uint4*)&Bs[stage][b_r][b_c + 4] = bu1;
            __syncthreads();
        }
    }

    // epilogue: acc layout — c0,c1 at (row g, col 2*tg,2*tg+1); c2,c3 at row g+8
    #pragma unroll
    for (int nj = 0; nj < 4; ++nj) {
        const int col = bn + wn * 32 + nj * 8 + 2 * tg;
        const float2 bi = *(const float2*)&bias[col];
        #pragma unroll
        for (int mi = 0; mi < 4; ++mi) {
            const int r0 = bm + wm * 64 + mi * 16 + g;
            const int r1 = r0 + 8;
            float2 o0 = make_float2(acc[mi][nj][0] + bi.x, acc[mi][nj][1] + bi.y);
            float2 o1 = make_float2(acc[mi][nj][2] + bi.x, acc[mi][nj][3] + bi.y);
            if (RES) {
                float2 q0 = *(const float2*)&Res[(size_t)r0 * N + col];
                float2 q1 = *(const float2*)&Res[(size_t)r1 * N + col];
                o0.x += q0.x; o0.y += q0.y;
                o1.x += q1.x; o1.y += q1.y;
            }
            if (RELU) {
                o0.x = fmaxf(o0.x, 0.f); o0.y = fmaxf(o0.y, 0.f);
                o1.x = fmaxf(o1.x, 0.f); o1.y = fmaxf(o1.y, 0.f);
            }
            *(float2*)&C[(size_t)r0 * N + col] = o0;
            *(float2*)&C[(size_t)r1 * N + col] = o1;
        }
    }
}

// ---------------- flash attention ------------------------------------------
// grid: (S/64, B*H), 256 threads. Q/K/V/ctx layout: [b, s, h, d] (d=64 contig).
#define ATT_ROWSTRIDE 68
#define ATT_SMEM ((4*64*ATT_ROWSTRIDE + 64) * 4)

__global__ void __launch_bounds__(256)
attn_kernel(const float* __restrict__ Qg, const float* __restrict__ Kg,
            const float* __restrict__ Vg, float* __restrict__ Cg)
{
    extern __shared__ float sm[];
    float* Qs = sm;
    float* Ks = sm + 64 * ATT_ROWSTRIDE;
    float* Vs = sm + 2 * 64 * ATT_ROWSTRIDE;
    float* Ps = sm + 3 * 64 * ATT_ROWSTRIDE;
    float* Cs = sm + 4 * 64 * ATT_ROWSTRIDE;   // per-row scalar (corr / lsum)

    const int tid  = threadIdx.x;
    const int w    = tid >> 5;
    const int lane = tid & 31;
    const int qt   = blockIdx.x;         // 0..7
    const int bh   = blockIdx.y;         // 0..255
    const int b    = bh >> 4;
    const int h    = bh & 15;

    const size_t headoff = ((size_t)b * Ssz * Hh + h) * DH;
    const int sstride = Hh * DH;         // 1024 floats per sequence step

    #pragma unroll
    for (int i = 0; i < 4; ++i) {
        int idx = tid + i * 256;
        int r = idx >> 4, c4 = (idx & 15) * 4;
        *(float4*)&Qs[r * ATT_ROWSTRIDE + c4] =
            *(const float4*)&Qg[headoff + (size_t)(qt * 64 + r) * sstride + c4];
    }

    float m[8], lden[8];
    #pragma unroll
    for (int r = 0; r < 8; ++r) { m[r] = -1e30f; lden[r] = 0.f; }
    float o0[8], o1[8];
    #pragma unroll
    for (int c = 0; c < 8; ++c) { o0[c] = 0.f; o1[c] = 0.f; }

    const int row0 = w * 8 + ((lane >> 3) << 1);  // this lane's O rows
    const int colA = (lane & 7) * 4;              // O cols colA..+3, colA+32..+35

    for (int kb = 0; kb < 8; ++kb) {
        __syncthreads();
        #pragma unroll
        for (int i = 0; i < 4; ++i) {
            int idx = tid + i * 256;
            int r = idx >> 4, c4 = (idx & 15) * 4;
            size_t gg = headoff + (size_t)(kb * 64 + r) * sstride + c4;
            *(float4*)&Ks[r * ATT_ROWSTRIDE + c4] = *(const float4*)&Kg[gg];
            *(float4*)&Vs[r * ATT_ROWSTRIDE + c4] = *(const float4*)&Vg[gg];
        }
        __syncthreads();

        float s0[8], s1[8];
        #pragma unroll
        for (int r = 0; r < 8; ++r) { s0[r] = 0.f; s1[r] = 0.f; }
        #pragma unroll
        for (int d4 = 0; d4 < 64; d4 += 4) {
            float4 k0 = *(const float4*)&Ks[lane * ATT_ROWSTRIDE + d4];
            float4 k1 = *(const float4*)&Ks[(lane + 32) * ATT_ROWSTRIDE + d4];
            #pragma unroll
            for (int r = 0; r < 8; ++r) {
                float4 q = *(const float4*)&Qs[(w * 8 + r) * ATT_ROWSTRIDE + d4];
                s0[r] += q.x * k0.x + q.y * k0.y + q.z * k0.z + q.w * k0.w;
                s1[r] += q.x * k1.x + q.y * k1.y + q.z * k1.z + q.w * k1.w;
            }
        }

        #pragma unroll
        for (int r = 0; r < 8; ++r) {
            float sa = s0[r] * 0.125f;
            float sb = s1[r] * 0.125f;
            float mx = fmaxf(sa, sb);
            #pragma unroll
            for (int off = 16; off; off >>= 1)
                mx = fmaxf(mx, __shfl_xor_sync(0xffffffffu, mx, off));
            float mnew = fmaxf(m[r], mx);
            float p0 = __expf(sa - mnew);
            float p1 = __expf(sb - mnew);
            float ps = p0 + p1;
            #pragma unroll
            for (int off = 16; off; off >>= 1)
                ps += __shfl_xor_sync(0xffffffffu, ps, off);
            float corr = __expf(m[r] - mnew);
            lden[r] = lden[r] * corr + ps;
            m[r] = mnew;
            Ps[(w * 8 + r) * ATT_ROWSTRIDE + lane]      = p0;
            Ps[(w * 8 + r) * ATT_ROWSTRIDE + lane + 32] = p1;
            if (lane == 0) Cs[w * 8 + r] = corr;
        }
        __syncwarp();

        float cr0 = Cs[row0];
        float cr1 = Cs[row0 + 1];
        #pragma unroll
        for (int c = 0; c < 8; ++c) { o0[c] *= cr0; o1[c] *= cr1; }

        #pragma unroll
        for (int kk4 = 0; kk4 < 64; kk4 += 4) {
            float4 pv0 = *(const float4*)&Ps[row0 * ATT_ROWSTRIDE + kk4];
            float4 pv1 = *(const float4*)&Ps[(row0 + 1) * ATT_ROWSTRIDE + kk4];
            float pa[4] = {pv0.x, pv0.y, pv0.z, pv0.w};
            float pb[4] = {pv1.x, pv1.y, pv1.z, pv1.w};
            #pragma unroll
            for (int j = 0; j < 4; ++j) {
                float4 va = *(const float4*)&Vs[(kk4 + j) * ATT_ROWSTRIDE + colA];
                float4 vb = *(const float4*)&Vs[(kk4 + j) * ATT_ROWSTRIDE + colA + 32];
                o0[0] += pa[j] * va.x; o0[1] += pa[j] * va.y;
                o0[2] += pa[j] * va.z; o0[3] += pa[j] * va.w;
                o0[4] += pa[j] * vb.x; o0[5] += pa[j] * vb.y;
                o0[6] += pa[j] * vb.z; o0[7] += pa[j] * vb.w;
                o1[0] += pb[j] * va.x; o1[1] += pb[j] * va.y;
                o1[2] += pb[j] * va.z; o1[3] += pb[j] * va.w;
                o1[4] += pb[j] * vb.x; o1[5] += pb[j] * vb.y;
                o1[6] += pb[j] * vb.z; o1[7] += pb[j] * vb.w;
            }
        }
        __syncwarp();
    }

    if (lane == 0) {
        #pragma unroll
        for (int r = 0; r < 8; ++r) Cs[w * 8 + r] = lden[r];
    }
    __syncwarp();
    float inv0 = 1.f / Cs[row0];
    float inv1 = 1.f / Cs[row0 + 1];

    size_t base0 = headoff + (size_t)(qt * 64 + row0) * sstride;
    size_t base1 = base0 + sstride;
    float4 out;
    out.x = o0[0]*inv0; out.y = o0[1]*inv0; out.z = o0[2]*inv0; out.w = o0[3]*inv0;
    *(float4*)&Cg[base0 + colA] = out;
    out.x = o0[4]*inv0; out.y = o0[5]*inv0; out.z = o0[6]*inv0; out.w = o0[7]*inv0;
    *(float4*)&Cg[base0 + colA + 32] = out;
    out.x = o1[0]*inv1; out.y = o1[1]*inv1; out.z = o1[2]*inv1; out.w = o1[3]*inv1;
    *(float4*)&Cg[base1 + colA] = out;
    out.x = o1[4]*inv1; out.y = o1[5]*inv1; out.z = o1[6]*inv1; out.w = o1[7]*inv1;
    *(float4*)&Cg[base1 + colA + 32] = out;
}

// ---------------- LayerNorm (one block per row of 1024) ---------------------
__device__ __forceinline__ float block_sum(float v, float* red)
{
    #pragma unroll
    for (int off = 16; off; off >>= 1)
        v += __shfl_xor_sync(0xffffffffu, v, off);
    __syncthreads();
    if ((threadIdx.x & 31) == 0) red[threadIdx.x >> 5] = v;
    __syncthreads();
    return red[0]+red[1]+red[2]+red[3]+red[4]+red[5]+red[6]+red[7];
}

__global__ void __launch_bounds__(256)
ln_kernel(const float* __restrict__ X, const float* __restrict__ gw,
          const float* __restrict__ bw, float* __restrict__ Y)
{
    __shared__ float red[8];
    const int row = blockIdx.x;
    const int tid = threadIdx.x;
    const size_t base = (size_t)row * Dsz + tid * 4;

    float4 v = *(const float4*)&X[base];
    float mean = block_sum(v.x + v.y + v.z + v.w, red) * (1.f / Dsz);
    float dx = v.x - mean, dy = v.y - mean, dz = v.z - mean, dw = v.w - mean;
    float var = block_sum(dx*dx + dy*dy + dz*dz + dw*dw, red) * (1.f / Dsz);
    float inv = rsqrtf(var + 1e-6f);

    float4 g4 = *(const float4*)&gw[tid * 4];
    float4 b4 = *(const float4*)&bw[tid * 4];
    float4 o;
    o.x = dx * inv * g4.x + b4.x;
    o.y = dy * inv * g4.y + b4.y;
    o.z = dz * inv * g4.z + b4.z;
    o.w = dw * inv * g4.w + b4.w;
    *(float4*)&Y[base] = o;
}

// ---------------- driver -----------------------------------------------------
extern "C" void kernel_launch(void* const* d_in, const int* in_sizes, int n_in,
                              void* d_out, int out_size)
{
    const float* hid  = (const float*)d_in[0];
    const float* Wq   = (const float*)d_in[1];
    const float* bq   = (const float*)d_in[2];
    const float* Wk   = (const float*)d_in[3];
    const float* bk   = (const float*)d_in[4];
    const float* Wv   = (const float*)d_in[5];
    const float* bv   = (const float*)d_in[6];
    const float* Wp   = (const float*)d_in[7];
    const float* bp   = (const float*)d_in[8];
    const float* g1   = (const float*)d_in[9];
    const float* be1  = (const float*)d_in[10];
    const float* W1   = (const float*)d_in[11];
    const float* b1   = (const float*)d_in[12];
    const float* W2   = (const float*)d_in[13];
    const float* b2   = (const float*)d_in[14];
    const float* g2   = (const float*)d_in[15];
    const float* be2  = (const float*)d_in[16];

    float *pX, *pQ, *pK, *pV, *pC, *pT, *pH;
    cudaGetSymbolAddress((void**)&pX, g_X);
    cudaGetSymbolAddress((void**)&pQ, g_Q);
    cudaGetSymbolAddress((void**)&pK, g_K);
    cudaGetSymbolAddress((void**)&pV, g_V);
    cudaGetSymbolAddress((void**)&pC, g_C);
    cudaGetSymbolAddress((void**)&pT, g_T);
    cudaGetSymbolAddress((void**)&pH, g_Hb);

    cudaFuncSetAttribute(attn_kernel,
                         cudaFuncAttributeMaxDynamicSharedMemorySize, ATT_SMEM);

    const size_t hbytes = sizeof(float) * (size_t)MROWS * Dsz;
    cudaMemcpyAsync(pX, hid, hbytes, cudaMemcpyDeviceToDevice);

    dim3 gD(Dsz / 128, MROWS / 128);   // (8, 64)
    dim3 gF(Ff  / 128, MROWS / 128);   // (32, 64)
    dim3 gA(Ssz / 64, Bsz * Hh);       // (8, 256)

    for (int l = 0; l < 4; ++l) {
        const float* wq = Wq + (size_t)l * Dsz * Dsz;
        const float* wk = Wk + (size_t)l * Dsz * Dsz;
        const float* wv = Wv + (size_t)l * Dsz * Dsz;
        const float* wp = Wp + (size_t)l * Dsz * Dsz;
        const float* w1 = W1 + (size_t)l * Dsz * Ff;
        const float* w2 = W2 + (size_t)l * Ff * Dsz;

        gemm_tf32<false,false><<<gD, 256>>>(pX, wq, bq + l*Dsz, nullptr, pQ, MROWS, Dsz, Dsz);
        gemm_tf32<false,false><<<gD, 256>>>(pX, wk, bk + l*Dsz, nullptr, pK, MROWS, Dsz, Dsz);
        gemm_tf32<false,false><<<gD, 256>>>(pX, wv, bv + l*Dsz, nullptr, pV, MROWS, Dsz, Dsz);

        attn_kernel<<<gA, 256, ATT_SMEM>>>(pQ, pK, pV, pC);

        gemm_tf32<false,true ><<<gD, 256>>>(pC, wp, bp + l*Dsz, pX, pT, MROWS, Dsz, Dsz);
        ln_kernel<<<MROWS, 256>>>(pT, g1 + l*Dsz, be1 + l*Dsz, pX);

        gemm_tf32<true ,false><<<gF, 256>>>(pX, w1, b1 + l*Ff, nullptr, pH, MROWS, Ff, Dsz);
        gemm_tf32<false,true ><<<gD, 256>>>(pH, w2, b2 + l*Dsz, pX, pT, MROWS, Dsz, Ff);
        ln_kernel<<<MROWS, 256>>>(pT, g2 + l*Dsz, be2 + l*Dsz, pX);
    }

    cudaMemcpyAsync((float*)d_out, pX, hbytes, cudaMemcpyDeviceToDevice);
}

// round 9
// speedup vs baseline: 2.1599x; 1.3046x over previous
#include <cuda_runtime.h>
#include <math.h>
#include <stdint.h>

#define Bsz 16
#define Ssz 512
#define Dsz 1024
#define Hh  16
#define Ff  4096
#define DH  64
#define MROWS (Bsz*Ssz)   // 8192

// ---------------- scratch (device-global; no allocation allowed) -------------
__device__ float g_X[MROWS*Dsz];
__device__ float g_Q[MROWS*Dsz];
__device__ float g_K[MROWS*Dsz];
__device__ float g_V[MROWS*Dsz];
__device__ float g_C[MROWS*Dsz];
__device__ float g_T[MROWS*Dsz];
__device__ float g_Hb[MROWS*Ff];

// ---------------- helpers ----------------------------------------------------
__device__ __forceinline__ uint32_t smem_u32(const void* p) {
    uint32_t a;
    asm("{ .reg .u64 t; cvta.to.shared.u64 t, %1; cvt.u32.u64 %0, t; }"
        : "=r"(a) : "l"(p));
    return a;
}
__device__ __forceinline__ uint32_t f2tf32(float x) {
    uint32_t u;
    asm("cvt.rna.tf32.f32 %0, %1;" : "=r"(u) : "f"(x));
    return u;
}
__device__ __forceinline__ void mma_tf32(float& c0, float& c1, float& c2, float& c3,
                                         uint32_t a0, uint32_t a1, uint32_t a2, uint32_t a3,
                                         uint32_t b0, uint32_t b1) {
    asm volatile(
        "mma.sync.aligned.m16n8k8.row.col.f32.tf32.tf32.f32 "
        "{%0,%1,%2,%3}, {%4,%5,%6,%7}, {%8,%9}, {%0,%1,%2,%3};"
        : "+f"(c0), "+f"(c1), "+f"(c2), "+f"(c3)
        : "r"(a0), "r"(a1), "r"(a2), "r"(a3), "r"(b0), "r"(b1));
}

#define CP_ASYNC16(dst_u32, src_ptr) \
    asm volatile("cp.async.cg.shared.global [%0], [%1], 16;" \
                 :: "r"(dst_u32), "l"(src_ptr))
#define CP_COMMIT()  asm volatile("cp.async.commit_group;" ::: "memory")
#define CP_WAIT2()   asm volatile("cp.async.wait_group 2;" ::: "memory")

// ---------------- pipelined TF32 mma.sync GEMM -------------------------------
// C[M,N] = A[M,K] @ W[K,N] + bias (+Res) (+ReLU). fp32 in/out, tf32 mma.
// BM=BN=128, BK=16, 4-stage cp.async pipeline, 256 thr = 8 warps (2m x 4n).
#define APAD 20              // A row stride in words (16 data + 4 pad)
#define BPAD 132             // B row stride in words (128 data + 4 pad)
#define A_STAGE_W (128*APAD) // 2560 words = 10240 B
#define B_STAGE_W (16*BPAD)  // 2112 words = 8448 B
#define GEMM_SMEM ((4*A_STAGE_W + 4*B_STAGE_W) * 4)   // 74752 B

template<bool RELU, bool RES>
__global__ void __launch_bounds__(256, 2)
gemm_pipe(const float* __restrict__ A, const float* __restrict__ Bm,
          const float* __restrict__ bias, const float* __restrict__ Res,
          float* __restrict__ C, int M, int N, int K)
{
    extern __shared__ float smf[];
    const uint32_t su = smem_u32(smf);

    const int tid  = threadIdx.x;
    const int warp = tid >> 5;
    const int lane = tid & 31;
    const int wm   = warp >> 2;        // 0..1
    const int wn   = warp & 3;         // 0..3
    const int g    = lane >> 2;        // 0..7
    const int tg   = lane & 3;         // 0..3

    const int bm = blockIdx.y * 128;
    const int bn = blockIdx.x * 128;
    const int NT = K >> 4;

    auto issue_stage = [&](int s) {
        const int bi = s & 3;
        const int k0 = s << 4;
        const uint32_t sA = su + (uint32_t)bi * (A_STAGE_W * 4);
        const uint32_t sB = su + (uint32_t)(4 * A_STAGE_W + bi * B_STAGE_W) * 4;
        #pragma unroll
        for (int j = 0; j < 2; ++j) {
            int c = tid + j * 256;               // 0..511
            int row = c >> 2;                    // 0..127
            int col = (c & 3) * 4;               // 0,4,8,12
            CP_ASYNC16(sA + (uint32_t)(row * APAD + col) * 4,
                       A + (size_t)(bm + row) * K + k0 + col);
        }
        #pragma unroll
        for (int j = 0; j < 2; ++j) {
            int c = tid + j * 256;               // 0..511
            int kr = c >> 5;                     // 0..15
            int nc = (c & 31) * 4;               // 0..124
            CP_ASYNC16(sB + (uint32_t)(kr * BPAD + nc) * 4,
                       Bm + (size_t)(k0 + kr) * N + bn + nc);
        }
    };

    // prologue: stages 0..2
    issue_stage(0); CP_COMMIT();
    issue_stage(1); CP_COMMIT();
    issue_stage(2); CP_COMMIT();

    float acc[4][4][4];
    #pragma unroll
    for (int i = 0; i < 4; ++i)
        #pragma unroll
        for (int j = 0; j < 4; ++j)
            #pragma unroll
            for (int e = 0; e < 4; ++e) acc[i][j][e] = 0.f;

    for (int t = 0; t < NT; ++t) {
        CP_WAIT2();
        __syncthreads();

        if (t + 3 < NT) issue_stage(t + 3);
        CP_COMMIT();

        const int bi = t & 3;
        const float* fA = smf + bi * A_STAGE_W;
        const float* fB = smf + 4 * A_STAGE_W + bi * B_STAGE_W;

        #pragma unroll
        for (int ks = 0; ks < 16; ks += 8) {
            uint32_t af[4][4];
            uint32_t bf[4][2];
            #pragma unroll
            for (int mi = 0; mi < 4; ++mi) {
                const int m0 = wm * 64 + mi * 16 + g;
                af[mi][0] = f2tf32(fA[m0 * APAD + ks + tg]);
                af[mi][1] = f2tf32(fA[(m0 + 8) * APAD + ks + tg]);
                af[mi][2] = f2tf32(fA[m0 * APAD + ks + tg + 4]);
                af[mi][3] = f2tf32(fA[(m0 + 8) * APAD + ks + tg + 4]);
            }
            #pragma unroll
            for (int nj = 0; nj < 4; ++nj) {
                const int cn = wn * 32 + nj * 8 + g;
                bf[nj][0] = f2tf32(fB[(ks + tg) * BPAD + cn]);
                bf[nj][1] = f2tf32(fB[(ks + tg + 4) * BPAD + cn]);
            }
            #pragma unroll
            for (int mi = 0; mi < 4; ++mi)
                #pragma unroll
                for (int nj = 0; nj < 4; ++nj)
                    mma_tf32(acc[mi][nj][0], acc[mi][nj][1], acc[mi][nj][2], acc[mi][nj][3],
                             af[mi][0], af[mi][1], af[mi][2], af[mi][3],
                             bf[nj][0], bf[nj][1]);
        }
    }

    // epilogue: c0,c1 at (row g, col 2tg, 2tg+1); c2,c3 at row g+8
    #pragma unroll
    for (int nj = 0; nj < 4; ++nj) {
        const int col = bn + wn * 32 + nj * 8 + 2 * tg;
        const float2 bi = *(const float2*)&bias[col];
        #pragma unroll
        for (int mi = 0; mi < 4; ++mi) {
            const int r0 = bm + wm * 64 + mi * 16 + g;
            const int r1 = r0 + 8;
            float2 o0 = make_float2(acc[mi][nj][0] + bi.x, acc[mi][nj][1] + bi.y);
            float2 o1 = make_float2(acc[mi][nj][2] + bi.x, acc[mi][nj][3] + bi.y);
            if (RES) {
                float2 q0 = *(const float2*)&Res[(size_t)r0 * N + col];
                float2 q1 = *(const float2*)&Res[(size_t)r1 * N + col];
                o0.x += q0.x; o0.y += q0.y;
                o1.x += q1.x; o1.y += q1.y;
            }
            if (RELU) {
                o0.x = fmaxf(o0.x, 0.f); o0.y = fmaxf(o0.y, 0.f);
                o1.x = fmaxf(o1.x, 0.f); o1.y = fmaxf(o1.y, 0.f);
            }
            *(float2*)&C[(size_t)r0 * N + col] = o0;
            *(float2*)&C[(size_t)r1 * N + col] = o1;
        }
    }
}

// ---------------- flash attention (unchanged) --------------------------------
#define ATT_ROWSTRIDE 68
#define ATT_SMEM ((4*64*ATT_ROWSTRIDE + 64) * 4)

__global__ void __launch_bounds__(256)
attn_kernel(const float* __restrict__ Qg, const float* __restrict__ Kg,
            const float* __restrict__ Vg, float* __restrict__ Cg)
{
    extern __shared__ float sm[];
    float* Qs = sm;
    float* Ks = sm + 64 * ATT_ROWSTRIDE;
    float* Vs = sm + 2 * 64 * ATT_ROWSTRIDE;
    float* Ps = sm + 3 * 64 * ATT_ROWSTRIDE;
    float* Cs = sm + 4 * 64 * ATT_ROWSTRIDE;

    const int tid  = threadIdx.x;
    const int w    = tid >> 5;
    const int lane = tid & 31;
    const int qt   = blockIdx.x;
    const int bh   = blockIdx.y;
    const int b    = bh >> 4;
    const int h    = bh & 15;

    const size_t headoff = ((size_t)b * Ssz * Hh + h) * DH;
    const int sstride = Hh * DH;

    #pragma unroll
    for (int i = 0; i < 4; ++i) {
        int idx = tid + i * 256;
        int r = idx >> 4, c4 = (idx & 15) * 4;
        *(float4*)&Qs[r * ATT_ROWSTRIDE + c4] =
            *(const float4*)&Qg[headoff + (size_t)(qt * 64 + r) * sstride + c4];
    }

    float m[8], lden[8];
    #pragma unroll
    for (int r = 0; r < 8; ++r) { m[r] = -1e30f; lden[r] = 0.f; }
    float o0[8], o1[8];
    #pragma unroll
    for (int c = 0; c < 8; ++c) { o0[c] = 0.f; o1[c] = 0.f; }

    const int row0 = w * 8 + ((lane >> 3) << 1);
    const int colA = (lane & 7) * 4;

    for (int kb = 0; kb < 8; ++kb) {
        __syncthreads();
        #pragma unroll
        for (int i = 0; i < 4; ++i) {
            int idx = tid + i * 256;
            int r = idx >> 4, c4 = (idx & 15) * 4;
            size_t gg = headoff + (size_t)(kb * 64 + r) * sstride + c4;
            *(float4*)&Ks[r * ATT_ROWSTRIDE + c4] = *(const float4*)&Kg[gg];
            *(float4*)&Vs[r * ATT_ROWSTRIDE + c4] = *(const float4*)&Vg[gg];
        }
        __syncthreads();

        float s0[8], s1[8];
        #pragma unroll
        for (int r = 0; r < 8; ++r) { s0[r] = 0.f; s1[r] = 0.f; }
        #pragma unroll
        for (int d4 = 0; d4 < 64; d4 += 4) {
            float4 k0 = *(const float4*)&Ks[lane * ATT_ROWSTRIDE + d4];
            float4 k1 = *(const float4*)&Ks[(lane + 32) * ATT_ROWSTRIDE + d4];
            #pragma unroll
            for (int r = 0; r < 8; ++r) {
                float4 q = *(const float4*)&Qs[(w * 8 + r) * ATT_ROWSTRIDE + d4];
                s0[r] += q.x * k0.x + q.y * k0.y + q.z * k0.z + q.w * k0.w;
                s1[r] += q.x * k1.x + q.y * k1.y + q.z * k1.z + q.w * k1.w;
            }
        }

        #pragma unroll
        for (int r = 0; r < 8; ++r) {
            float sa = s0[r] * 0.125f;
            float sb = s1[r] * 0.125f;
            float mx = fmaxf(sa, sb);
            #pragma unroll
            for (int off = 16; off; off >>= 1)
                mx = fmaxf(mx, __shfl_xor_sync(0xffffffffu, mx, off));
            float mnew = fmaxf(m[r], mx);
            float p0 = __expf(sa - mnew);
            float p1 = __expf(sb - mnew);
            float ps = p0 + p1;
            #pragma unroll
            for (int off = 16; off; off >>= 1)
                ps += __shfl_xor_sync(0xffffffffu, ps, off);
            float corr = __expf(m[r] - mnew);
            lden[r] = lden[r] * corr + ps;
            m[r] = mnew;
            Ps[(w * 8 + r) * ATT_ROWSTRIDE + lane]      = p0;
            Ps[(w * 8 + r) * ATT_ROWSTRIDE + lane + 32] = p1;
            if (lane == 0) Cs[w * 8 + r] = corr;
        }
        __syncwarp();

        float cr0 = Cs[row0];
        float cr1 = Cs[row0 + 1];
        #pragma unroll
        for (int c = 0; c < 8; ++c) { o0[c] *= cr0; o1[c] *= cr1; }

        #pragma unroll
        for (int kk4 = 0; kk4 < 64; kk4 += 4) {
            float4 pv0 = *(const float4*)&Ps[row0 * ATT_ROWSTRIDE + kk4];
            float4 pv1 = *(const float4*)&Ps[(row0 + 1) * ATT_ROWSTRIDE + kk4];
            float pa[4] = {pv0.x, pv0.y, pv0.z, pv0.w};
            float pb[4] = {pv1.x, pv1.y, pv1.z, pv1.w};
            #pragma unroll
            for (int j = 0; j < 4; ++j) {
                float4 va = *(const float4*)&Vs[(kk4 + j) * ATT_ROWSTRIDE + colA];
                float4 vb = *(const float4*)&Vs[(kk4 + j) * ATT_ROWSTRIDE + colA + 32];
                o0[0] += pa[j] * va.x; o0[1] += pa[j] * va.y;
                o0[2] += pa[j] * va.z; o0[3] += pa[j] * va.w;
                o0[4] += pa[j] * vb.x; o0[5] += pa[j] * vb.y;
                o0[6] += pa[j] * vb.z; o0[7] += pa[j] * vb.w;
                o1[0] += pb[j] * va.x; o1[1] += pb[j] * va.y;
                o1[2] += pb[j] * va.z; o1[3] += pb[j] * va.w;
                o1[4] += pb[j] * vb.x; o1[5] += pb[j] * vb.y;
                o1[6] += pb[j] * vb.z; o1[7] += pb[j] * vb.w;
            }
        }
        __syncwarp();
    }

    if (lane == 0) {
        #pragma unroll
        for (int r = 0; r < 8; ++r) Cs[w * 8 + r] = lden[r];
    }
    __syncwarp();
    float inv0 = 1.f / Cs[row0];
    float inv1 = 1.f / Cs[row0 + 1];

    size_t base0 = headoff + (size_t)(qt * 64 + row0) * sstride;
    size_t base1 = base0 + sstride;
    float4 out;
    out.x = o0[0]*inv0; out.y = o0[1]*inv0; out.z = o0[2]*inv0; out.w = o0[3]*inv0;
    *(float4*)&Cg[base0 + colA] = out;
    out.x = o0[4]*inv0; out.y = o0[5]*inv0; out.z = o0[6]*inv0; out.w = o0[7]*inv0;
    *(float4*)&Cg[base0 + colA + 32] = out;
    out.x = o1[0]*inv1; out.y = o1[1]*inv1; out.z = o1[2]*inv1; out.w = o1[3]*inv1;
    *(float4*)&Cg[base1 + colA] = out;
    out.x = o1[4]*inv1; out.y = o1[5]*inv1; out.z = o1[6]*inv1; out.w = o1[7]*inv1;
    *(float4*)&Cg[base1 + colA + 32] = out;
}

// ---------------- LayerNorm ---------------------------------------------------
__device__ __forceinline__ float block_sum(float v, float* red)
{
    #pragma unroll
    for (int off = 16; off; off >>= 1)
        v += __shfl_xor_sync(0xffffffffu, v, off);
    __syncthreads();
    if ((threadIdx.x & 31) == 0) red[threadIdx.x >> 5] = v;
    __syncthreads();
    return red[0]+red[1]+red[2]+red[3]+red[4]+red[5]+red[6]+red[7];
}

__global__ void __launch_bounds__(256)
ln_kernel(const float* __restrict__ X, const float* __restrict__ gw,
          const float* __restrict__ bw, float* __restrict__ Y)
{
    __shared__ float red[8];
    const int row = blockIdx.x;
    const int tid = threadIdx.x;
    const size_t base = (size_t)row * Dsz + tid * 4;

    float4 v = *(const float4*)&X[base];
    float mean = block_sum(v.x + v.y + v.z + v.w, red) * (1.f / Dsz);
    float dx = v.x - mean, dy = v.y - mean, dz = v.z - mean, dw = v.w - mean;
    float var = block_sum(dx*dx + dy*dy + dz*dz + dw*dw, red) * (1.f / Dsz);
    float inv = rsqrtf(var + 1e-6f);

    float4 g4 = *(const float4*)&gw[tid * 4];
    float4 b4 = *(const float4*)&bw[tid * 4];
    float4 o;
    o.x = dx * inv * g4.x + b4.x;
    o.y = dy * inv * g4.y + b4.y;
    o.z = dz * inv * g4.z + b4.z;
    o.w = dw * inv * g4.w + b4.w;
    *(float4*)&Y[base] = o;
}

// ---------------- driver -----------------------------------------------------
extern "C" void kernel_launch(void* const* d_in, const int* in_sizes, int n_in,
                              void* d_out, int out_size)
{
    const float* hid  = (const float*)d_in[0];
    const float* Wq   = (const float*)d_in[1];
    const float* bq   = (const float*)d_in[2];
    const float* Wk   = (const float*)d_in[3];
    const float* bk   = (const float*)d_in[4];
    const float* Wv   = (const float*)d_in[5];
    const float* bv   = (const float*)d_in[6];
    const float* Wp   = (const float*)d_in[7];
    const float* bp   = (const float*)d_in[8];
    const float* g1   = (const float*)d_in[9];
    const float* be1  = (const float*)d_in[10];
    const float* W1   = (const float*)d_in[11];
    const float* b1   = (const float*)d_in[12];
    const float* W2   = (const float*)d_in[13];
    const float* b2   = (const float*)d_in[14];
    const float* g2   = (const float*)d_in[15];
    const float* be2  = (const float*)d_in[16];

    float *pX, *pQ, *pK, *pV, *pC, *pT, *pH;
    cudaGetSymbolAddress((void**)&pX, g_X);
    cudaGetSymbolAddress((void**)&pQ, g_Q);
    cudaGetSymbolAddress((void**)&pK, g_K);
    cudaGetSymbolAddress((void**)&pV, g_V);
    cudaGetSymbolAddress((void**)&pC, g_C);
    cudaGetSymbolAddress((void**)&pT, g_T);
    cudaGetSymbolAddress((void**)&pH, g_Hb);

    cudaFuncSetAttribute(attn_kernel,
                         cudaFuncAttributeMaxDynamicSharedMemorySize, ATT_SMEM);
    cudaFuncSetAttribute(gemm_pipe<false,false>,
                         cudaFuncAttributeMaxDynamicSharedMemorySize, GEMM_SMEM);
    cudaFuncSetAttribute(gemm_pipe<false,true>,
                         cudaFuncAttributeMaxDynamicSharedMemorySize, GEMM_SMEM);
    cudaFuncSetAttribute(gemm_pipe<true,false>,
                         cudaFuncAttributeMaxDynamicSharedMemorySize, GEMM_SMEM);

    const size_t hbytes = sizeof(float) * (size_t)MROWS * Dsz;
    cudaMemcpyAsync(pX, hid, hbytes, cudaMemcpyDeviceToDevice);

    dim3 gD(Dsz / 128, MROWS / 128);   // (8, 64)
    dim3 gF(Ff  / 128, MROWS / 128);   // (32, 64)
    dim3 gA(Ssz / 64, Bsz * Hh);       // (8, 256)

    for (int l = 0; l < 4; ++l) {
        const float* wq = Wq + (size_t)l * Dsz * Dsz;
        const float* wk = Wk + (size_t)l * Dsz * Dsz;
        const float* wv = Wv + (size_t)l * Dsz * Dsz;
        const float* wp = Wp + (size_t)l * Dsz * Dsz;
        const float* w1 = W1 + (size_t)l * Dsz * Ff;
        const float* w2 = W2 + (size_t)l * Ff * Dsz;

        gemm_pipe<false,false><<<gD, 256, GEMM_SMEM>>>(pX, wq, bq + l*Dsz, nullptr, pQ, MROWS, Dsz, Dsz);
        gemm_pipe<false,false><<<gD, 256, GEMM_SMEM>>>(pX, wk, bk + l*Dsz, nullptr, pK, MROWS, Dsz, Dsz);
        gemm_pipe<false,false><<<gD, 256, GEMM_SMEM>>>(pX, wv, bv + l*Dsz, nullptr, pV, MROWS, Dsz, Dsz);

        attn_kernel<<<gA, 256, ATT_SMEM>>>(pQ, pK, pV, pC);

        gemm_pipe<false,true ><<<gD, 256, GEMM_SMEM>>>(pC, wp, bp + l*Dsz, pX, pT, MROWS, Dsz, Dsz);
        ln_kernel<<<MROWS, 256>>>(pT, g1 + l*Dsz, be1 + l*Dsz, pX);

        gemm_pipe<true ,false><<<gF, 256, GEMM_SMEM>>>(pX, w1, b1 + l*Ff, nullptr, pH, MROWS, Ff, Dsz);
        gemm_pipe<false,true ><<<gD, 256, GEMM_SMEM>>>(pH, w2, b2 + l*Dsz, pX, pT, MROWS, Dsz, Ff);
        ln_kernel<<<MROWS, 256>>>(pT, g2 + l*Dsz, be2 + l*Dsz, pX);
    }

    cudaMemcpyAsync((float*)d_out, pX, hbytes, cudaMemcpyDeviceToDevice);
}